// round 16
// baseline (speedup 1.0000x reference)
#include <cuda_runtime.h>
#include <cuda_fp16.h>
#include <cstdint>

// SigLipLoss: loss = (1/N) * sum_ij softplus(s_ij), sign-flip on diagonal.
// Round 15: 256x256 CTA tile, 512 threads, warp 64x64 (4x4), 1 CTA/SM,
// BK=64 with 3-stage cp.async pipeline. Halves barriers/MAC and cuts
// crossbar to 0.076 B/MAC vs R11. Certify-one-ahead barrier (kk3 frags
// cross in registers), fp16 mma.sync, fp16x2 epilogue, desync partials.

#define NN 8192
#define DD 768
#define BM 256
#define BN 256
#define BK 64
#define NROWT (NN / BM)               // 32
#define NCOLT (NN / BN)               // 32
#define NTILES (NROWT * NCOLT)        // 1024
#define KITERS (DD / BK)              // 12
#define NCTA 148
#define ROWBYTES (DD * 2)             // 1536

#define A_B   (BM * 128)              // 32768
#define STAGE_B ((BM + BN) * 128)     // 65536
#define STAGES 3
#define SMEM_TOTAL (STAGES * STAGE_B + 128)

__device__ __align__(16) __half g_Ahf[NN * DD];
__device__ __align__(16) __half g_Bhf[NN * DD];
__device__ float g_partials16[NTILES * 16];
__device__ unsigned g_done;

__device__ __forceinline__ uint32_t smem_u32(const void* p) {
    uint32_t r;
    asm("{ .reg .u64 t; cvta.to.shared.u64 t, %1; cvt.u32.u64 %0, t; }"
        : "=r"(r) : "l"(p));
    return r;
}
__device__ __forceinline__ void cpa16(uint32_t dst, const void* src) {
    asm volatile("cp.async.cg.shared.global [%0], [%1], 16;"
                 :: "r"(dst), "l"(__cvta_generic_to_global(src)) : "memory");
}
__device__ __forceinline__ void ldm_x4(uint32_t* r, uint32_t addr) {
    asm volatile("ldmatrix.sync.aligned.m8n8.x4.shared.b16 {%0,%1,%2,%3}, [%4];"
                 : "=r"(r[0]), "=r"(r[1]), "=r"(r[2]), "=r"(r[3]) : "r"(addr));
}
__device__ __forceinline__ void mma16816h(uint32_t* c, const uint32_t* a,
                                          const uint32_t* b) {
    asm volatile(
        "mma.sync.aligned.m16n8k16.row.col.f16.f16.f16.f16 "
        "{%0,%1}, {%2,%3,%4,%5}, {%6,%7}, {%0,%1};"
        : "+r"(c[0]), "+r"(c[1])
        : "r"(a[0]), "r"(a[1]), "r"(a[2]), "r"(a[3]), "r"(b[0]), "r"(b[1]));
}
__device__ __forceinline__ __half2 sp_h2exp2(__half2 x) {
    uint32_t r, xi = *(uint32_t*)&x;
    asm("ex2.approx.f16x2 %0, %1;" : "=r"(r) : "r"(xi));
    return *(__half2*)&r;
}

__global__ void convert_kernel(const float* __restrict__ A,
                               const float* __restrict__ B) {
    if (blockIdx.x == 0 && threadIdx.x == 0) g_done = 0;
    const int total4 = NN * DD / 4;
    const int stride = gridDim.x * blockDim.x;
    __half2* pa = (__half2*)g_Ahf;
    __half2* pb = (__half2*)g_Bhf;
    for (int i = blockIdx.x * blockDim.x + threadIdx.x; i < total4; i += stride) {
        float4 a = ((const float4*)A)[i];
        float4 b = ((const float4*)B)[i];
        pa[2 * i + 0] = __floats2half2_rn(a.x, a.y);
        pa[2 * i + 1] = __floats2half2_rn(a.z, a.w);
        pb[2 * i + 0] = __floats2half2_rn(b.x, b.y);
        pb[2 * i + 1] = __floats2half2_rn(b.z, b.w);
    }
}

__global__ __launch_bounds__(512, 1) void siglip_mma_kernel(float* __restrict__ out) {
    extern __shared__ char smem_raw[];
    __shared__ unsigned s_last;
    uint32_t sbase = smem_u32(smem_raw);
    sbase = (sbase + 127u) & ~127u;

    const int tid  = threadIdx.x;
    const int wid  = tid >> 5;
    const int lane = tid & 31;
    const int warp_m = wid & 3;          // 4 m-groups of 64 rows
    const int warp_n = wid >> 2;         // 4 n-groups of 64 cols
    const int cta = blockIdx.x;

    const int ntiles = (NTILES - cta + NCTA - 1) / NCTA;
    const int C = ntiles * KITERS;

    // ---- producer mapping: 8x 16B per thread per chunk (A:4, B:4) ----
    const int rp   = tid & 255;          // tile row 0..255 (for both A and B)
    const int half = tid >> 8;           // 0..1: which 64B half of the 128B row
    const uint32_t rp7 = (uint32_t)(rp & 7);
    const uint32_t cBo = (uint32_t)(half * 64);
    uint32_t dA[4], dB[4];
#pragma unroll
    for (int i = 0; i < 4; ++i) {
        uint32_t c = (uint32_t)(half * 4 + i);
        dA[i] = rp * 128 + ((c ^ rp7) * 16);
        dB[i] = A_B + rp * 128 + ((c ^ rp7) * 16);
    }

    int pKB = 0, pG = cta, issued = 0;
    const char* bA0 = (const char*)g_Ahf
        + ((size_t)(pG >> 5) * BM + rp) * ROWBYTES + cBo;
    const char* bB0 = (const char*)g_Bhf
        + ((size_t)(pG & 31) * BN + rp) * ROWBYTES + cBo;

#define ISSUE() do {                                                        \
        const uint32_t stb = sbase + (uint32_t)(issued % 3) * STAGE_B;      \
        _Pragma("unroll")                                                   \
        for (int i = 0; i < 4; ++i) cpa16(stb + dA[i], bA0 + pKB + i * 16); \
        _Pragma("unroll")                                                   \
        for (int i = 0; i < 4; ++i) cpa16(stb + dB[i], bB0 + pKB + i * 16); \
        asm volatile("cp.async.commit_group;" ::: "memory");                \
        ++issued;                                                           \
        pKB += 128;                                                         \
        if (pKB == DD * 2) {                                                \
            pKB = 0; pG += NCTA;                                            \
            if (pG < NTILES) {                                              \
                bA0 = (const char*)g_Ahf                                    \
                    + ((size_t)(pG >> 5) * BM + rp) * ROWBYTES + cBo;       \
                bB0 = (const char*)g_Bhf                                    \
                    + ((size_t)(pG & 31) * BN + rp) * ROWBYTES + cBo;       \
            }                                                               \
        }                                                                   \
    } while (0)

    // ---- ldmatrix per-lane addresses (SW128 xor on 128B rows) ----
    const int rowA = warp_m * 64 + (lane & 15);
    const uint32_t ra7 = (uint32_t)(rowA & 7);
    const uint32_t ca = (uint32_t)(lane >> 4);
    uint32_t aAddr[4];
#pragma unroll
    for (int kk = 0; kk < 4; ++kk)
        aAddr[kk] = rowA * 128 + (((2u * kk + ca) ^ ra7) * 16);

    const int rowB = warp_n * 64 + (lane & 7) + ((lane >> 4) & 1) * 8;
    const uint32_t rb7 = (uint32_t)(rowB & 7);
    const uint32_t cb = (uint32_t)((lane >> 3) & 1);
    uint32_t bAddr[4];
#pragma unroll
    for (int kk = 0; kk < 4; ++kk)
        bAddr[kk] = A_B + rowB * 128 + (((2u * kk + cb) ^ rb7) * 16);

    // ---- prologue: fill 3 stages, certify chunk 0 ----
    ISSUE(); ISSUE(); ISSUE();
    asm volatile("cp.async.wait_group 2;" ::: "memory");
    __syncthreads();

    int ch = 0;
    int g = cta;
#pragma unroll 1
    for (int t = 0; t < ntiles; ++t, g += NCTA) {
        uint32_t acc[4][8][2];
#pragma unroll
        for (int mt = 0; mt < 4; ++mt)
#pragma unroll
            for (int nt = 0; nt < 8; ++nt) { acc[mt][nt][0] = 0u; acc[mt][nt][1] = 0u; }

#pragma unroll 1
        for (int it = 0; it < KITERS; ++it, ++ch) {
            const uint32_t sS = sbase + (uint32_t)(ch % 3) * STAGE_B;
            uint32_t a[4][4], b[4][4];

            // kk = 0..2: load + MMA
#pragma unroll
            for (int kk = 0; kk < 3; ++kk) {
#pragma unroll
                for (int mt = 0; mt < 4; ++mt)
                    ldm_x4(a[mt], sS + aAddr[kk] + mt * 2048);
#pragma unroll
                for (int np = 0; np < 4; ++np)
                    ldm_x4(b[np], sS + bAddr[kk] + np * 2048);
#pragma unroll
                for (int mt = 0; mt < 4; ++mt)
#pragma unroll
                    for (int nt = 0; nt < 8; ++nt)
                        mma16816h(acc[mt][nt], a[mt], &b[nt >> 1][(nt & 1) * 2]);
            }

            // kk = 3: load fragments (they survive the barrier in registers)
#pragma unroll
            for (int mt = 0; mt < 4; ++mt)
                ldm_x4(a[mt], sS + aAddr[3] + mt * 2048);
#pragma unroll
            for (int np = 0; np < 4; ++np)
                ldm_x4(b[np], sS + bAddr[3] + np * 2048);

            // certify chunk ch+1; quiesce readers of stage ch%3; refill it
            if (ch + 3 <= C) asm volatile("cp.async.wait_group 1;" ::: "memory");
            else             asm volatile("cp.async.wait_group 0;" ::: "memory");
            __syncthreads();
            if (issued < C) ISSUE();

            // kk = 3 MMA: pure tensor work flowing out of the barrier
#pragma unroll
            for (int mt = 0; mt < 4; ++mt)
#pragma unroll
                for (int nt = 0; nt < 8; ++nt)
                    mma16816h(acc[mt][nt], a[mt], &b[nt >> 1][(nt & 1) * 2]);
        }

        // ---- de-synchronized epilogue (no barriers) ----
        const float SCALE = 2.302585092994046f, BIAS = -10.0f;
        const __half2 S2  = __floats2half2_rn(SCALE, SCALE);
        const __half2 Bi2 = __floats2half2_rn(BIAS, BIAS);
        const __half2 NL2 = __floats2half2_rn(-1.4426950408889634f,
                                              -1.4426950408889634f);
        const __half2 ONE2 = __floats2half2_rn(1.0f, 1.0f);
        const __half2 ZERO2 = __floats2half2_rn(0.0f, 0.0f);
        float lsum = 0.0f;
#pragma unroll
        for (int mt = 0; mt < 4; ++mt) {
#pragma unroll
            for (int q = 0; q < 4; ++q) {
                __half2 zz[4];
#pragma unroll
                for (int h = 0; h < 2; ++h)
#pragma unroll
                    for (int v = 0; v < 2; ++v)
                        zz[h * 2 + v] = __hfma2(
                            *(const __half2*)&acc[mt][2 * q + h][v], S2, Bi2);
                __half2 s2 = __hadd2(
                    __hadd2(__hmax2(zz[0], ZERO2), __hmax2(zz[1], ZERO2)),
                    __hadd2(__hmax2(zz[2], ZERO2), __hmax2(zz[3], ZERO2)));
                float2 fs = __half22float2(s2);
                lsum += fs.x + fs.y;
                __half2 p2 = __hmul2(
                    __hmul2(__hadd2(sp_h2exp2(__hmul2(__habs2(zz[0]), NL2)), ONE2),
                            __hadd2(sp_h2exp2(__hmul2(__habs2(zz[1]), NL2)), ONE2)),
                    __hmul2(__hadd2(sp_h2exp2(__hmul2(__habs2(zz[2]), NL2)), ONE2),
                            __hadd2(sp_h2exp2(__hmul2(__habs2(zz[3]), NL2)), ONE2)));
                float2 fp = __half22float2(p2);
                lsum += __logf(fp.x * fp.y);
            }
        }
        if ((g >> 5) == (g & 31)) {   // diagonal tile: softplus(-z)=softplus(z)-z
#pragma unroll
            for (int mt = 0; mt < 4; ++mt) {
                const int row = warp_m * 64 + mt * 16 + (lane >> 2);
#pragma unroll
                for (int nt = 0; nt < 8; ++nt) {
                    const int col0 = warp_n * 64 + nt * 8 + (lane & 3) * 2;
#pragma unroll
                    for (int v = 0; v < 2; ++v) {
                        const int r_ = row + v * 8;
                        if (r_ == col0 || r_ == col0 + 1) {
                            float2 f = __half22float2(
                                *(const __half2*)&acc[mt][nt][v]);
                            float zd = (r_ == col0) ? fmaf(f.x, SCALE, BIAS)
                                                    : fmaf(f.y, SCALE, BIAS);
                            lsum -= zd;
                        }
                    }
                }
            }
        }
#pragma unroll
        for (int off = 16; off > 0; off >>= 1)
            lsum += __shfl_down_sync(0xFFFFFFFFu, lsum, off);
        if (lane == 0) g_partials16[g * 16 + wid] = lsum;
    }
#undef ISSUE

    // ---- last CTA out performs the deterministic finalize ----
    __threadfence();
    __syncthreads();
    if (tid == 0)
        s_last = (atomicAdd(&g_done, 1u) == NCTA - 1) ? 1u : 0u;
    __syncthreads();
    if (s_last) {
        __threadfence();
        double* sd = (double*)smem_raw;    // stage buffers dead
        double s = 0.0;
        for (int i = tid; i < NTILES * 16; i += 512)
            s += (double)g_partials16[i];
        sd[tid] = s;
        __syncthreads();
#pragma unroll
        for (int off = 256; off > 0; off >>= 1) {
            if (tid < off) sd[tid] += sd[tid + off];
            __syncthreads();
        }
        if (tid == 0) out[0] = (float)(sd[0] / (double)NN);
    }
}

extern "C" void kernel_launch(void* const* d_in, const int* in_sizes, int n_in,
                              void* d_out, int out_size) {
    cudaFuncSetAttribute(siglip_mma_kernel,
                         cudaFuncAttributeMaxDynamicSharedMemorySize, SMEM_TOTAL);
    convert_kernel<<<2048, 256>>>((const float*)d_in[0], (const float*)d_in[1]);
    siglip_mma_kernel<<<NCTA, 512, SMEM_TOTAL>>>((float*)d_out);
}

// round 17
// speedup vs baseline: 1.5738x; 1.5738x over previous
#include <cuda_runtime.h>
#include <cuda_fp16.h>
#include <cstdint>

// SigLipLoss: loss = (1/N) * sum_ij softplus(s_ij), sign-flip on diagonal.
// Round 16: R11 skeleton (128x256, 2x256-thread CTAs/SM, BK=64, 2 stages,
// certify-one-ahead) + kk3-MMA SPLIT around the barrier: 16 MMAs before the
// __syncthreads absorb LDSM-completion spread, 16 after give post-barrier
// runway. fp16 mma.sync, fp16x2 epilogue, desync partials, folded finalize.

#define NN 8192
#define DD 768
#define BM 128
#define BN 256
#define BK 64
#define NROWT (NN / BM)               // 64
#define NCOLT (NN / BN)               // 32
#define NTILES (NROWT * NCOLT)        // 2048
#define KITERS (DD / BK)              // 12
#define NCTA 296
#define ROWBYTES (DD * 2)             // 1536

#define A_B   (BM * 128)              // 16384
#define STAGE_B ((BM + BN) * 128)     // 49152
#define SMEM_TOTAL (2 * STAGE_B + 128)

__device__ __align__(16) __half g_Ahf[NN * DD];
__device__ __align__(16) __half g_Bhf[NN * DD];
__device__ float g_partials8[NTILES * 8];
__device__ unsigned g_done;

__device__ __forceinline__ uint32_t smem_u32(const void* p) {
    uint32_t r;
    asm("{ .reg .u64 t; cvta.to.shared.u64 t, %1; cvt.u32.u64 %0, t; }"
        : "=r"(r) : "l"(p));
    return r;
}
__device__ __forceinline__ void cpa16(uint32_t dst, const void* src) {
    asm volatile("cp.async.cg.shared.global [%0], [%1], 16;"
                 :: "r"(dst), "l"(__cvta_generic_to_global(src)) : "memory");
}
__device__ __forceinline__ void ldm_x4(uint32_t* r, uint32_t addr) {
    asm volatile("ldmatrix.sync.aligned.m8n8.x4.shared.b16 {%0,%1,%2,%3}, [%4];"
                 : "=r"(r[0]), "=r"(r[1]), "=r"(r[2]), "=r"(r[3]) : "r"(addr));
}
__device__ __forceinline__ void mma16816h(uint32_t* c, const uint32_t* a,
                                          const uint32_t* b) {
    asm volatile(
        "mma.sync.aligned.m16n8k16.row.col.f16.f16.f16.f16 "
        "{%0,%1}, {%2,%3,%4,%5}, {%6,%7}, {%0,%1};"
        : "+r"(c[0]), "+r"(c[1])
        : "r"(a[0]), "r"(a[1]), "r"(a[2]), "r"(a[3]), "r"(b[0]), "r"(b[1]));
}
__device__ __forceinline__ __half2 sp_h2exp2(__half2 x) {
    uint32_t r, xi = *(uint32_t*)&x;
    asm("ex2.approx.f16x2 %0, %1;" : "=r"(r) : "r"(xi));
    return *(__half2*)&r;
}

__global__ void convert_kernel(const float* __restrict__ A,
                               const float* __restrict__ B) {
    if (blockIdx.x == 0 && threadIdx.x == 0) g_done = 0;
    const int total4 = NN * DD / 4;
    const int stride = gridDim.x * blockDim.x;
    __half2* pa = (__half2*)g_Ahf;
    __half2* pb = (__half2*)g_Bhf;
    for (int i = blockIdx.x * blockDim.x + threadIdx.x; i < total4; i += stride) {
        float4 a = ((const float4*)A)[i];
        float4 b = ((const float4*)B)[i];
        pa[2 * i + 0] = __floats2half2_rn(a.x, a.y);
        pa[2 * i + 1] = __floats2half2_rn(a.z, a.w);
        pb[2 * i + 0] = __floats2half2_rn(b.x, b.y);
        pb[2 * i + 1] = __floats2half2_rn(b.z, b.w);
    }
}

__global__ __launch_bounds__(256, 2) void siglip_mma_kernel(float* __restrict__ out) {
    extern __shared__ char smem_raw[];
    __shared__ unsigned s_last;
    uint32_t sbase = smem_u32(smem_raw);
    sbase = (sbase + 127u) & ~127u;

    const int tid  = threadIdx.x;
    const int wid  = tid >> 5;
    const int lane = tid & 31;
    const int warp_m = wid & 1;          // 2 m-groups of 64 rows
    const int warp_n = wid >> 1;         // 4 n-groups of 64 cols
    const int cta = blockIdx.x;

    const int ntiles = (NTILES - cta + NCTA - 1) / NCTA;
    const int C = ntiles * KITERS;

    // ---- producer mapping: 12x 16B per thread per chunk (A:4, B:8) ----
    const int r0 = tid >> 3;             // 0..31
    const int c8 = tid & 7;              // 16B col within 128B row
    const uint32_t colp = (uint32_t)((c8 ^ (r0 & 7)) * 16);
    const uint32_t dstA = r0 * 128 + colp;
    const uint32_t dstB = A_B + r0 * 128 + colp;
    const uint32_t cBo = c8 * 16;

    int pKB = 0, pG = cta, issued = 0;
    const char* bA0 = (const char*)g_Ahf
        + ((size_t)(pG >> 5) * BM + r0) * ROWBYTES + cBo;
    const char* bB0 = (const char*)g_Bhf
        + ((size_t)(pG & 31) * BN + r0) * ROWBYTES + cBo;

#define ISSUE() do {                                                        \
        const uint32_t stb = sbase + (uint32_t)(issued & 1) * STAGE_B;      \
        _Pragma("unroll")                                                   \
        for (int i = 0; i < 4; ++i)                                         \
            cpa16(stb + dstA + i * 4096,                                    \
                  bA0 + (size_t)i * 32 * ROWBYTES + pKB);                   \
        _Pragma("unroll")                                                   \
        for (int i = 0; i < 8; ++i)                                         \
            cpa16(stb + dstB + i * 4096,                                    \
                  bB0 + (size_t)i * 32 * ROWBYTES + pKB);                   \
        asm volatile("cp.async.commit_group;" ::: "memory");                \
        ++issued;                                                           \
        pKB += 128;                                                         \
        if (pKB == DD * 2) {                                                \
            pKB = 0; pG += NCTA;                                            \
            if (pG < NTILES) {                                              \
                bA0 = (const char*)g_Ahf                                    \
                    + ((size_t)(pG >> 5) * BM + r0) * ROWBYTES + cBo;       \
                bB0 = (const char*)g_Bhf                                    \
                    + ((size_t)(pG & 31) * BN + r0) * ROWBYTES + cBo;       \
            }                                                               \
        }                                                                   \
    } while (0)

    // ---- ldmatrix per-lane addresses (SW128-style xor on 128B rows) ----
    const int rowA = warp_m * 64 + (lane & 15);
    const uint32_t ra7 = (uint32_t)(rowA & 7);
    const uint32_t ca = (uint32_t)(lane >> 4);
    uint32_t aAddr[4];
#pragma unroll
    for (int kk = 0; kk < 4; ++kk)
        aAddr[kk] = rowA * 128 + (((2u * kk + ca) ^ ra7) * 16);

    const int rowB = warp_n * 64 + (lane & 7) + ((lane >> 4) & 1) * 8;
    const uint32_t rb7 = (uint32_t)(lane & 7);
    const uint32_t cb = (uint32_t)((lane >> 3) & 1);
    uint32_t bAddr[4];
#pragma unroll
    for (int kk = 0; kk < 4; ++kk)
        bAddr[kk] = A_B + rowB * 128 + (((2u * kk + cb) ^ rb7) * 16);

    // ---- prologue: fill both stages, certify chunk 0 ----
    ISSUE(); ISSUE();
    asm volatile("cp.async.wait_group 1;" ::: "memory");
    __syncthreads();

    int ch = 0;
    int g = cta;
#pragma unroll 1
    for (int t = 0; t < ntiles; ++t, g += NCTA) {
        uint32_t acc[4][8][2];
#pragma unroll
        for (int mt = 0; mt < 4; ++mt)
#pragma unroll
            for (int nt = 0; nt < 8; ++nt) { acc[mt][nt][0] = 0u; acc[mt][nt][1] = 0u; }

#pragma unroll 1
        for (int it = 0; it < KITERS; ++it, ++ch) {
            const uint32_t sS = sbase + (uint32_t)(ch & 1) * STAGE_B;
            uint32_t a[4][4], b[4][4];

            // kk = 0..2: load + MMA
#pragma unroll
            for (int kk = 0; kk < 3; ++kk) {
#pragma unroll
                for (int mt = 0; mt < 4; ++mt)
                    ldm_x4(a[mt], sS + aAddr[kk] + mt * 2048);
#pragma unroll
                for (int np = 0; np < 4; ++np)
                    ldm_x4(b[np], sS + bAddr[kk] + np * 2048);
#pragma unroll
                for (int mt = 0; mt < 4; ++mt)
#pragma unroll
                    for (int nt = 0; nt < 8; ++nt)
                        mma16816h(acc[mt][nt], a[mt], &b[nt >> 1][(nt & 1) * 2]);
            }

            // kk = 3: load fragments (all reads of stage ch&1 complete here)
#pragma unroll
            for (int mt = 0; mt < 4; ++mt)
                ldm_x4(a[mt], sS + aAddr[3] + mt * 2048);
#pragma unroll
            for (int np = 0; np < 4; ++np)
                ldm_x4(b[np], sS + bAddr[3] + np * 2048);

            // kk3 MMA FIRST HALF: pre-barrier runway absorbing LDSM spread
#pragma unroll
            for (int mt = 0; mt < 2; ++mt)
#pragma unroll
                for (int nt = 0; nt < 8; ++nt)
                    mma16816h(acc[mt][nt], a[mt], &b[nt >> 1][(nt & 1) * 2]);

            // certify chunk ch+1; quiesce readers of stage ch&1; refill it
            asm volatile("cp.async.wait_group 0;" ::: "memory");
            __syncthreads();
            if (issued < C) ISSUE();

            // kk3 MMA SECOND HALF: post-barrier runway
#pragma unroll
            for (int mt = 2; mt < 4; ++mt)
#pragma unroll
                for (int nt = 0; nt < 8; ++nt)
                    mma16816h(acc[mt][nt], a[mt], &b[nt >> 1][(nt & 1) * 2]);
        }

        // ---- de-synchronized epilogue (no barriers) ----
        const float SCALE = 2.302585092994046f, BIAS = -10.0f;
        const __half2 S2  = __floats2half2_rn(SCALE, SCALE);
        const __half2 Bi2 = __floats2half2_rn(BIAS, BIAS);
        const __half2 NL2 = __floats2half2_rn(-1.4426950408889634f,
                                              -1.4426950408889634f);
        const __half2 ONE2 = __floats2half2_rn(1.0f, 1.0f);
        const __half2 ZERO2 = __floats2half2_rn(0.0f, 0.0f);
        float lsum = 0.0f;
#pragma unroll
        for (int mt = 0; mt < 4; ++mt) {
#pragma unroll
            for (int q = 0; q < 4; ++q) {
                __half2 zz[4];
#pragma unroll
                for (int h = 0; h < 2; ++h)
#pragma unroll
                    for (int v = 0; v < 2; ++v)
                        zz[h * 2 + v] = __hfma2(
                            *(const __half2*)&acc[mt][2 * q + h][v], S2, Bi2);
                __half2 s2 = __hadd2(
                    __hadd2(__hmax2(zz[0], ZERO2), __hmax2(zz[1], ZERO2)),
                    __hadd2(__hmax2(zz[2], ZERO2), __hmax2(zz[3], ZERO2)));
                float2 fs = __half22float2(s2);
                lsum += fs.x + fs.y;
                __half2 p2 = __hmul2(
                    __hmul2(__hadd2(sp_h2exp2(__hmul2(__habs2(zz[0]), NL2)), ONE2),
                            __hadd2(sp_h2exp2(__hmul2(__habs2(zz[1]), NL2)), ONE2)),
                    __hmul2(__hadd2(sp_h2exp2(__hmul2(__habs2(zz[2]), NL2)), ONE2),
                            __hadd2(sp_h2exp2(__hmul2(__habs2(zz[3]), NL2)), ONE2)));
                float2 fp = __half22float2(p2);
                lsum += __logf(fp.x * fp.y);
            }
        }
        if ((g >> 6) == (g & 31)) {   // diagonal tile: softplus(-z)=softplus(z)-z
            const int rowOff = ((g >> 5) & 1) * 128;
#pragma unroll
            for (int mt = 0; mt < 4; ++mt) {
                const int row = rowOff + warp_m * 64 + mt * 16 + (lane >> 2);
#pragma unroll
                for (int nt = 0; nt < 8; ++nt) {
                    const int col0 = warp_n * 64 + nt * 8 + (lane & 3) * 2;
#pragma unroll
                    for (int v = 0; v < 2; ++v) {
                        const int r_ = row + v * 8;
                        if (r_ == col0 || r_ == col0 + 1) {
                            float2 f = __half22float2(
                                *(const __half2*)&acc[mt][nt][v]);
                            float zd = (r_ == col0) ? fmaf(f.x, SCALE, BIAS)
                                                    : fmaf(f.y, SCALE, BIAS);
                            lsum -= zd;
                        }
                    }
                }
            }
        }
#pragma unroll
        for (int off = 16; off > 0; off >>= 1)
            lsum += __shfl_down_sync(0xFFFFFFFFu, lsum, off);
        if (lane == 0) g_partials8[g * 8 + wid] = lsum;
    }
#undef ISSUE

    // ---- last CTA out performs the deterministic finalize ----
    __threadfence();
    __syncthreads();
    if (tid == 0)
        s_last = (atomicAdd(&g_done, 1u) == NCTA - 1) ? 1u : 0u;
    __syncthreads();
    if (s_last) {
        __threadfence();
        double* sd = (double*)smem_raw;    // stage buffers dead
        double s = 0.0;
        for (int i = tid; i < NTILES * 8; i += 256)
            s += (double)g_partials8[i];
        sd[tid] = s;
        __syncthreads();
#pragma unroll
        for (int off = 128; off > 0; off >>= 1) {
            if (tid < off) sd[tid] += sd[tid + off];
            __syncthreads();
        }
        if (tid == 0) out[0] = (float)(sd[0] / (double)NN);
    }
}

extern "C" void kernel_launch(void* const* d_in, const int* in_sizes, int n_in,
                              void* d_out, int out_size) {
    cudaFuncSetAttribute(siglip_mma_kernel,
                         cudaFuncAttributeMaxDynamicSharedMemorySize, SMEM_TOTAL);
    convert_kernel<<<2048, 256>>>((const float*)d_in[0], (const float*)d_in[1]);
    siglip_mma_kernel<<<NCTA, 256, SMEM_TOTAL>>>((float*)d_out);
}